// round 12
// baseline (speedup 1.0000x reference)
#include <cuda_runtime.h>
#include <cstdint>

#define NN     100000
#define NE     1600000
#define H      64
#define SCD    6
#define ED     16
#define NL     2
#define MSGIN  156
#define NG     128
#define NSCANB ((NN + 1023) / 1024)   // 98

typedef unsigned long long u64;

__device__ float g_h[NN * H];
__device__ float g_P[NN * H];
__device__ float g_Q[NN * H];
__device__ float g_S[NN * H];
__device__ float g_cnt[NN];
__device__ int   g_deg[NN];
__device__ int   g_off[NN + 1];
__device__ int   g_cur[NN];
__device__ int   g_bsum[NSCANB];
__device__ int2  g_cse[NE];            // (src, ew_bits) CSR-by-dst order
__device__ float g_efp[NE * ED + 32];  // edge_feature permuted to CSR order

// ---- f32x2 helpers (node GEMMs only) -------------------------------------
__device__ __forceinline__ u64 pack2(float x) {
    u64 r; asm("mov.b64 %0, {%1, %1};" : "=l"(r) : "f"(x)); return r;
}
__device__ __forceinline__ u64 pack_pair(float lo, float hi) {
    u64 r; asm("mov.b64 %0, {%1, %2};" : "=l"(r) : "f"(lo), "f"(hi)); return r;
}
__device__ __forceinline__ float2 unpack_pair(u64 v) {
    float2 f; asm("mov.b64 {%0, %1}, %2;" : "=f"(f.x), "=f"(f.y) : "l"(v)); return f;
}
__device__ __forceinline__ void fma2(u64& a, u64 b, u64 c) {
    asm("fma.rn.f32x2 %0, %1, %2, %0;" : "+l"(a) : "l"(b), "l"(c));
}
__device__ __forceinline__ void red_add_v2(float* p, float a, float b) {
    asm volatile("red.global.add.v2.f32 [%0], {%1, %2};"
                 :: "l"(p), "f"(a), "f"(b) : "memory");
}

// ---- fork/join stream resources (created at static init, pre-checkpoint) --
struct StreamRes {
    cudaStream_t s2 = nullptr;
    cudaEvent_t ev_fork = nullptr, ev_join = nullptr;
    bool ok = false;
    StreamRes() {
        if (cudaStreamCreateWithFlags(&s2, cudaStreamNonBlocking) != cudaSuccess) return;
        if (cudaEventCreateWithFlags(&ev_fork, cudaEventDisableTiming) != cudaSuccess) return;
        if (cudaEventCreateWithFlags(&ev_join, cudaEventDisableTiming) != cudaSuccess) return;
        ok = true;
    }
};
static StreamRes g_sr;

// ---------------------------------------------------------------------------
// CSR build chain
// ---------------------------------------------------------------------------
__global__ void k_zero(float* __restrict__ out) {
    int i = blockIdx.x * blockDim.x + threadIdx.x;
    if (i < NN) g_deg[i] = 0;
    if (i < NG * H) out[i] = 0.f;
}

__global__ void k_deg(const int* __restrict__ el) {
    int e = blockIdx.x * blockDim.x + threadIdx.x;
    if (e < NE) atomicAdd(&g_deg[el[2 * e + 1]], 1);
}

__global__ void k_scan_a() {
    __shared__ int wsum[8];
    int b = blockIdx.x, t = threadIdx.x, lane = t & 31, wid = t >> 5;
    int base = b * 1024 + t * 4;
    int s = 0;
#pragma unroll
    for (int j = 0; j < 4; j++) { int n = base + j; if (n < NN) s += g_deg[n]; }
#pragma unroll
    for (int d = 16; d > 0; d >>= 1) s += __shfl_down_sync(~0u, s, d);
    if (lane == 0) wsum[wid] = s;
    __syncthreads();
    if (t == 0) {
        int tot = 0;
#pragma unroll
        for (int w = 0; w < 8; w++) tot += wsum[w];
        g_bsum[b] = tot;
    }
}

__global__ void k_scan_b() {   // 1 warp
    int lane = threadIdx.x;
    int v[4];
    int base = lane * 4;
#pragma unroll
    for (int j = 0; j < 4; j++) v[j] = (base + j < NSCANB) ? g_bsum[base + j] : 0;
    int s = v[0] + v[1] + v[2] + v[3];
    int incl = s;
#pragma unroll
    for (int d = 1; d < 32; d <<= 1) {
        int x = __shfl_up_sync(~0u, incl, d);
        if (lane >= d) incl += x;
    }
    int off = incl - s;
#pragma unroll
    for (int j = 0; j < 4; j++) {
        if (base + j < NSCANB) g_bsum[base + j] = off;
        off += v[j];
    }
}

__global__ void k_scan_c() {
    __shared__ int warp_tot[8];
    __shared__ int warp_off[8];
    int b = blockIdx.x, t = threadIdx.x, lane = t & 31, wid = t >> 5;
    int base = b * 1024 + t * 4;
    int v0 = 0, v1 = 0, v2 = 0, v3 = 0;
    if (base + 0 < NN) v0 = g_deg[base + 0];
    if (base + 1 < NN) v1 = g_deg[base + 1];
    if (base + 2 < NN) v2 = g_deg[base + 2];
    if (base + 3 < NN) v3 = g_deg[base + 3];
    int s = v0 + v1 + v2 + v3;
    int incl = s;
#pragma unroll
    for (int d = 1; d < 32; d <<= 1) {
        int x = __shfl_up_sync(~0u, incl, d);
        if (lane >= d) incl += x;
    }
    if (lane == 31) warp_tot[wid] = incl;
    __syncthreads();
    if (wid == 0) {
        int wt = (lane < 8) ? warp_tot[lane] : 0;
        int wincl = wt;
#pragma unroll
        for (int d = 1; d < 8; d <<= 1) {
            int x = __shfl_up_sync(~0u, wincl, d);
            if (lane >= d) wincl += x;
        }
        if (lane < 8) warp_off[lane] = wincl - wt;
    }
    __syncthreads();
    int off = g_bsum[b] + warp_off[wid] + (incl - s);
    if (base + 0 < NN) { g_off[base + 0] = off; g_cur[base + 0] = off; } off += v0;
    if (base + 1 < NN) { g_off[base + 1] = off; g_cur[base + 1] = off; } off += v1;
    if (base + 2 < NN) { g_off[base + 2] = off; g_cur[base + 2] = off; } off += v2;
    if (base + 3 < NN) { g_off[base + 3] = off; g_cur[base + 3] = off; }
    if (b == 0 && t == 0) g_off[NN] = NE;
}

__global__ void k_scatter(const int* __restrict__ el, const float* __restrict__ ef,
                          const float* __restrict__ ew) {
    int e = blockIdx.x * blockDim.x + threadIdx.x;
    if (e < NE) {
        int2 sd = ((const int2*)el)[e];
        int pos = atomicAdd(&g_cur[sd.y], 1);
        g_cse[pos] = make_int2(sd.x, __float_as_int(ew[e]));
        const float4* s4 = (const float4*)&ef[(size_t)e * ED];
        float4* d4 = (float4*)&g_efp[(size_t)pos * ED];
        d4[0] = s4[0]; d4[1] = s4[1]; d4[2] = s4[2]; d4[3] = s4[3];
    }
}

// ---------------------------------------------------------------------------
// h0 = x @ lin_w + lin_b   — 4 nodes/warp, f32x2 (r9 version)
// ---------------------------------------------------------------------------
__global__ void k_h0(const float* __restrict__ x, const float* __restrict__ w,
                     const float* __restrict__ b) {
    __shared__ __align__(16) float sW[H * H];
    __shared__ float sB[H];
    __shared__ __align__(16) float sin_[8][4][H];
    for (int i = threadIdx.x; i < H * H; i += blockDim.x) sW[i] = w[i];
    for (int i = threadIdx.x; i < H; i += blockDim.x) sB[i] = b[i];
    __syncthreads();

    int wid = threadIdx.x >> 5, lane = threadIdx.x & 31;
    int nwarps = (blockDim.x >> 5) * gridDim.x;
    int gw = blockIdx.x * (blockDim.x >> 5) + wid;
    for (int t = gw; t < NN / 4; t += nwarps) {
        int base = t * 4;
#pragma unroll
        for (int j = 0; j < 4; j++) {
            float2 xv = *(const float2*)&x[(base + j) * H + 2 * lane];
            sin_[wid][j][2 * lane] = xv.x;
            sin_[wid][j][2 * lane + 1] = xv.y;
        }
        __syncwarp();
        u64 A[4];
        u64 bini = pack_pair(sB[2 * lane], sB[2 * lane + 1]);
#pragma unroll
        for (int j = 0; j < 4; j++) A[j] = bini;
#pragma unroll
        for (int i = 0; i < H; i += 4) {
            u64 w0 = *(const u64*)&sW[(i + 0) * H + 2 * lane];
            u64 w1 = *(const u64*)&sW[(i + 1) * H + 2 * lane];
            u64 w2 = *(const u64*)&sW[(i + 2) * H + 2 * lane];
            u64 w3 = *(const u64*)&sW[(i + 3) * H + 2 * lane];
#pragma unroll
            for (int j = 0; j < 4; j++) {
                float4 v = *(const float4*)&sin_[wid][j][i];
                fma2(A[j], pack2(v.x), w0);
                fma2(A[j], pack2(v.y), w1);
                fma2(A[j], pack2(v.z), w2);
                fma2(A[j], pack2(v.w), w3);
            }
        }
#pragma unroll
        for (int j = 0; j < 4; j++)
            *(float2*)&g_h[(base + j) * H + 2 * lane] = unpack_pair(A[j]);
        __syncwarp();
    }
}

// ---------------------------------------------------------------------------
// P = h@Wa + sc@Wc + b1 ; Q = h@Wb + sc@Wd   — 4 nodes/warp, f32x2 (r9)
// ---------------------------------------------------------------------------
__global__ void k_pq(const float* __restrict__ w1, const float* __restrict__ b1,
                     const int* __restrict__ nstruct) {
    __shared__ __align__(16) float sWP[(H + SCD) * H];
    __shared__ __align__(16) float sWQ[(H + SCD) * H];
    __shared__ float sB1[H];
    __shared__ __align__(16) float sin_[8][4][72];
    for (int i = threadIdx.x; i < H * H; i += blockDim.x) {
        sWP[i] = w1[i];
        sWQ[i] = w1[H * H + i];
    }
    for (int i = threadIdx.x; i < SCD * H; i += blockDim.x) {
        sWP[H * H + i] = w1[2 * H * H + i];
        sWQ[H * H + i] = w1[2 * H * H + SCD * H + i];
    }
    for (int i = threadIdx.x; i < H; i += blockDim.x) sB1[i] = b1[i];
    __syncthreads();

    int wid = threadIdx.x >> 5, lane = threadIdx.x & 31;
    int nwarps = (blockDim.x >> 5) * gridDim.x;
    int gw = blockIdx.x * (blockDim.x >> 5) + wid;
    for (int t = gw; t < NN / 4; t += nwarps) {
        int base = t * 4;
#pragma unroll
        for (int j = 0; j < 4; j++) {
            int n = base + j;
            float2 hv = *(const float2*)&g_h[n * H + 2 * lane];
            sin_[wid][j][2 * lane] = hv.x;
            sin_[wid][j][2 * lane + 1] = hv.y;
            if (lane < SCD) sin_[wid][j][H + lane] = (float)nstruct[n * SCD + lane];
        }
        __syncwarp();
        u64 P[4], Q[4];
        u64 bini = pack_pair(sB1[2 * lane], sB1[2 * lane + 1]);
#pragma unroll
        for (int j = 0; j < 4; j++) { P[j] = bini; Q[j] = 0ull; }
#pragma unroll 4
        for (int i = 0; i < H; i += 4) {
            u64 wp0 = *(const u64*)&sWP[(i + 0) * H + 2 * lane];
            u64 wp1 = *(const u64*)&sWP[(i + 1) * H + 2 * lane];
            u64 wp2 = *(const u64*)&sWP[(i + 2) * H + 2 * lane];
            u64 wp3 = *(const u64*)&sWP[(i + 3) * H + 2 * lane];
            u64 wq0 = *(const u64*)&sWQ[(i + 0) * H + 2 * lane];
            u64 wq1 = *(const u64*)&sWQ[(i + 1) * H + 2 * lane];
            u64 wq2 = *(const u64*)&sWQ[(i + 2) * H + 2 * lane];
            u64 wq3 = *(const u64*)&sWQ[(i + 3) * H + 2 * lane];
#pragma unroll
            for (int j = 0; j < 4; j++) {
                float4 v = *(const float4*)&sin_[wid][j][i];
                u64 v0 = pack2(v.x), v1 = pack2(v.y), v2 = pack2(v.z), v3 = pack2(v.w);
                fma2(P[j], v0, wp0); fma2(Q[j], v0, wq0);
                fma2(P[j], v1, wp1); fma2(Q[j], v1, wq1);
                fma2(P[j], v2, wp2); fma2(Q[j], v2, wq2);
                fma2(P[j], v3, wp3); fma2(Q[j], v3, wq3);
            }
        }
#pragma unroll
        for (int i = H; i < H + SCD; i++) {
            u64 wp = *(const u64*)&sWP[i * H + 2 * lane];
            u64 wq = *(const u64*)&sWQ[i * H + 2 * lane];
#pragma unroll
            for (int j = 0; j < 4; j++) {
                u64 vv = pack2(sin_[wid][j][i]);
                fma2(P[j], vv, wp);
                fma2(Q[j], vv, wq);
            }
        }
#pragma unroll
        for (int j = 0; j < 4; j++) {
            int n = base + j;
            *(float2*)&g_P[n * H + 2 * lane] = unpack_pair(P[j]);
            *(float2*)&g_Q[n * H + 2 * lane] = unpack_pair(Q[j]);
        }
        __syncwarp();
    }
}

// ---------------------------------------------------------------------------
// Edge pass: CSR by dst, warp per node, 4-edge SOFTWARE-PIPELINED mainloop
//   S[n] = sum ew * relu(P[src] + Q[n] + ef @ We) ;  cnt[n] = sum ew
// ---------------------------------------------------------------------------
struct EdgeBatch {
    int4 c01, c23;
    float m0, m1;
    float2 p0, p1, p2, p3;
};

__device__ __forceinline__ void load_batch(EdgeBatch& b, int k, int lane) {
    b.c01 = *(const int4*)&g_cse[k];
    b.c23 = *(const int4*)&g_cse[k + 2];
    b.m0 = g_efp[(size_t)k * ED + lane];
    b.m1 = g_efp[(size_t)(k + 2) * ED + lane];
    b.p0 = *(const float2*)&g_P[(size_t)b.c01.x * H + 2 * lane];
    b.p1 = *(const float2*)&g_P[(size_t)b.c01.z * H + 2 * lane];
    b.p2 = *(const float2*)&g_P[(size_t)b.c23.x * H + 2 * lane];
    b.p3 = *(const float2*)&g_P[(size_t)b.c23.z * H + 2 * lane];
}

__device__ __forceinline__ void compute_batch(
    const EdgeBatch& b, float2 q, const float* wr0, const float* wr1,
    float& acc0, float& acc1, float& cw) {
    float a00 = b.p0.x + q.x, a01 = b.p0.y + q.y;
    float a10 = b.p1.x + q.x, a11 = b.p1.y + q.y;
    float a20 = b.p2.x + q.x, a21 = b.p2.y + q.y;
    float a30 = b.p3.x + q.x, a31 = b.p3.y + q.y;
#pragma unroll
    for (int i = 0; i < ED; i++) {
        float v0 = __shfl_sync(0xffffffffu, b.m0, i);
        float v1 = __shfl_sync(0xffffffffu, b.m0, ED + i);
        float v2 = __shfl_sync(0xffffffffu, b.m1, i);
        float v3 = __shfl_sync(0xffffffffu, b.m1, ED + i);
        a00 = fmaf(v0, wr0[i], a00);
        a01 = fmaf(v0, wr1[i], a01);
        a10 = fmaf(v1, wr0[i], a10);
        a11 = fmaf(v1, wr1[i], a11);
        a20 = fmaf(v2, wr0[i], a20);
        a21 = fmaf(v2, wr1[i], a21);
        a30 = fmaf(v3, wr0[i], a30);
        a31 = fmaf(v3, wr1[i], a31);
    }
    float w0 = __int_as_float(b.c01.y), w1 = __int_as_float(b.c01.w);
    float w2 = __int_as_float(b.c23.y), w3 = __int_as_float(b.c23.w);
    acc0 = fmaf(fmaxf(a00, 0.f), w0, acc0);
    acc1 = fmaf(fmaxf(a01, 0.f), w0, acc1);
    acc0 = fmaf(fmaxf(a10, 0.f), w1, acc0);
    acc1 = fmaf(fmaxf(a11, 0.f), w1, acc1);
    acc0 = fmaf(fmaxf(a20, 0.f), w2, acc0);
    acc1 = fmaf(fmaxf(a21, 0.f), w2, acc1);
    acc0 = fmaf(fmaxf(a30, 0.f), w3, acc0);
    acc1 = fmaf(fmaxf(a31, 0.f), w3, acc1);
    cw += (w0 + w1) + (w2 + w3);
}

__device__ __forceinline__ void edge_single(
    int k, int lane, float2 q, const float* wr0, const float* wr1,
    float& acc0, float& acc1, float& cw) {
    int2 s0 = g_cse[k];
    float myef = (lane < ED) ? g_efp[(size_t)k * ED + lane] : 0.f;
    float2 p0 = *(const float2*)&g_P[(size_t)s0.x * H + 2 * lane];
    float a00 = p0.x + q.x, a01 = p0.y + q.y;
#pragma unroll
    for (int i = 0; i < ED; i++) {
        float v0 = __shfl_sync(0xffffffffu, myef, i);
        a00 = fmaf(v0, wr0[i], a00);
        a01 = fmaf(v0, wr1[i], a01);
    }
    float w0 = __int_as_float(s0.y);
    acc0 = fmaf(fmaxf(a00, 0.f), w0, acc0);
    acc1 = fmaf(fmaxf(a01, 0.f), w0, acc1);
    cw += w0;
}

__global__ void __launch_bounds__(256) k_edge_csr(const float* __restrict__ We_g) {
    int wid = threadIdx.x >> 5, lane = threadIdx.x & 31;
    float wr0[ED], wr1[ED];
#pragma unroll
    for (int i = 0; i < ED; i++) {
        float2 wv = *(const float2*)&We_g[i * H + 2 * lane];
        wr0[i] = wv.x; wr1[i] = wv.y;
    }

    int nwarps = (blockDim.x >> 5) * gridDim.x;
    int gw = blockIdx.x * (blockDim.x >> 5) + wid;
    for (int n = gw; n < NN; n += nwarps) {
        int row = g_off[n], end = g_off[n + 1];
        float2 q = *(const float2*)&g_Q[n * H + 2 * lane];
        float acc0 = 0.f, acc1 = 0.f, cw = 0.f;
        int k = row;
        if ((k & 1) && k < end) {                      // peel odd head → k even
            edge_single(k, lane, q, wr0, wr1, acc0, acc1, cw);
            k++;
        }
        // ---- software-pipelined 4-edge mainloop ----
        if (k + 4 <= end) {
            EdgeBatch cur;
            load_batch(cur, k, lane);
            k += 4;
            for (; k + 4 <= end; k += 4) {
                EdgeBatch nxt;
                load_batch(nxt, k, lane);              // issue next-batch loads
                compute_batch(cur, q, wr0, wr1, acc0, acc1, cw);
                cur = nxt;
            }
            compute_batch(cur, q, wr0, wr1, acc0, acc1, cw);
        }
        // ---- 2-edge tail ----
        if (k + 2 <= end) {
            int4 c01 = *(const int4*)&g_cse[k];
            float m0 = g_efp[(size_t)k * ED + lane];
            float2 p0 = *(const float2*)&g_P[(size_t)c01.x * H + 2 * lane];
            float2 p1 = *(const float2*)&g_P[(size_t)c01.z * H + 2 * lane];
            float a00 = p0.x + q.x, a01 = p0.y + q.y;
            float a10 = p1.x + q.x, a11 = p1.y + q.y;
#pragma unroll
            for (int i = 0; i < ED; i++) {
                float v0 = __shfl_sync(0xffffffffu, m0, i);
                float v1 = __shfl_sync(0xffffffffu, m0, ED + i);
                a00 = fmaf(v0, wr0[i], a00);
                a01 = fmaf(v0, wr1[i], a01);
                a10 = fmaf(v1, wr0[i], a10);
                a11 = fmaf(v1, wr1[i], a11);
            }
            float w0 = __int_as_float(c01.y), w1 = __int_as_float(c01.w);
            acc0 = fmaf(fmaxf(a00, 0.f), w0, acc0);
            acc1 = fmaf(fmaxf(a01, 0.f), w0, acc1);
            acc0 = fmaf(fmaxf(a10, 0.f), w1, acc0);
            acc1 = fmaf(fmaxf(a11, 0.f), w1, acc1);
            cw += w0 + w1;
            k += 2;
        }
        if (k < end)                                   // single tail
            edge_single(k, lane, q, wr0, wr1, acc0, acc1, cw);

        *(float2*)&g_S[n * H + 2 * lane] = make_float2(acc0, acc1);
        if (lane == 0) g_cnt[n] = cw;
    }
}

// ---------------------------------------------------------------------------
// upd = S@W2 + cnt*b2 ; t = relu([h,upd]@U1+ub1) ; h = relu(t@U2+ub2)  (r9)
// ---------------------------------------------------------------------------
__global__ void k_upd(const float* __restrict__ w2g, const float* __restrict__ b2,
                      const float* __restrict__ u1g, const float* __restrict__ ub1,
                      const float* __restrict__ u2g, const float* __restrict__ ub2) {
    extern __shared__ float sm[];
    float* sW2 = sm;
    float* sU1 = sm + 4096;
    float* sU2 = sm + 12288;
    float* sB2 = sm + 16384;
    float* sUB1 = sm + 16448;
    float* sUB2 = sm + 16512;
    float* sbuf = sm + 16576;

    for (int i = threadIdx.x; i < H * H; i += blockDim.x) { sW2[i] = w2g[i]; sU2[i] = u2g[i]; }
    for (int i = threadIdx.x; i < 2 * H * H; i += blockDim.x) sU1[i] = u1g[i];
    for (int i = threadIdx.x; i < H; i += blockDim.x) {
        sB2[i] = b2[i]; sUB1[i] = ub1[i]; sUB2[i] = ub2[i];
    }
    __syncthreads();

    int wid = threadIdx.x >> 5, lane = threadIdx.x & 31;
    float* buf = sbuf + wid * 512;
    int nwarps = (blockDim.x >> 5) * gridDim.x;
    int gw = blockIdx.x * (blockDim.x >> 5) + wid;
    for (int t = gw; t < NN / 4; t += nwarps) {
        int base = t * 4;
        float cnt[4];
#pragma unroll
        for (int j = 0; j < 4; j++) {
            int n = base + j;
            float2 sv = *(const float2*)&g_S[n * H + 2 * lane];
            buf[j * 128 + 2 * lane] = sv.x;
            buf[j * 128 + 2 * lane + 1] = sv.y;
            cnt[j] = g_cnt[n];
        }
        __syncwarp();
        float bb0 = sB2[2 * lane], bb1 = sB2[2 * lane + 1];
        u64 U[4];
#pragma unroll
        for (int j = 0; j < 4; j++) U[j] = pack_pair(cnt[j] * bb0, cnt[j] * bb1);
#pragma unroll 4
        for (int i = 0; i < H; i += 4) {
            u64 w0 = *(const u64*)&sW2[(i + 0) * H + 2 * lane];
            u64 w1 = *(const u64*)&sW2[(i + 1) * H + 2 * lane];
            u64 w2 = *(const u64*)&sW2[(i + 2) * H + 2 * lane];
            u64 w3 = *(const u64*)&sW2[(i + 3) * H + 2 * lane];
#pragma unroll
            for (int j = 0; j < 4; j++) {
                float4 v = *(const float4*)&buf[j * 128 + i];
                fma2(U[j], pack2(v.x), w0);
                fma2(U[j], pack2(v.y), w1);
                fma2(U[j], pack2(v.z), w2);
                fma2(U[j], pack2(v.w), w3);
            }
        }
        __syncwarp();
#pragma unroll
        for (int j = 0; j < 4; j++) {
            int n = base + j;
            float2 hv = *(const float2*)&g_h[n * H + 2 * lane];
            float2 uv = unpack_pair(U[j]);
            buf[j * 128 + 2 * lane] = hv.x;
            buf[j * 128 + 2 * lane + 1] = hv.y;
            buf[j * 128 + H + 2 * lane] = uv.x;
            buf[j * 128 + H + 2 * lane + 1] = uv.y;
        }
        __syncwarp();
        u64 T[4];
        u64 tb = pack_pair(sUB1[2 * lane], sUB1[2 * lane + 1]);
#pragma unroll
        for (int j = 0; j < 4; j++) T[j] = tb;
#pragma unroll 4
        for (int i = 0; i < 2 * H; i += 4) {
            u64 w0 = *(const u64*)&sU1[(i + 0) * H + 2 * lane];
            u64 w1 = *(const u64*)&sU1[(i + 1) * H + 2 * lane];
            u64 w2 = *(const u64*)&sU1[(i + 2) * H + 2 * lane];
            u64 w3 = *(const u64*)&sU1[(i + 3) * H + 2 * lane];
#pragma unroll
            for (int j = 0; j < 4; j++) {
                float4 v = *(const float4*)&buf[j * 128 + i];
                fma2(T[j], pack2(v.x), w0);
                fma2(T[j], pack2(v.y), w1);
                fma2(T[j], pack2(v.z), w2);
                fma2(T[j], pack2(v.w), w3);
            }
        }
        __syncwarp();
#pragma unroll
        for (int j = 0; j < 4; j++) {
            float2 tv = unpack_pair(T[j]);
            buf[j * 128 + 2 * lane] = fmaxf(tv.x, 0.f);
            buf[j * 128 + 2 * lane + 1] = fmaxf(tv.y, 0.f);
        }
        __syncwarp();
        u64 Z[4];
        u64 zb = pack_pair(sUB2[2 * lane], sUB2[2 * lane + 1]);
#pragma unroll
        for (int j = 0; j < 4; j++) Z[j] = zb;
#pragma unroll 4
        for (int i = 0; i < H; i += 4) {
            u64 w0 = *(const u64*)&sU2[(i + 0) * H + 2 * lane];
            u64 w1 = *(const u64*)&sU2[(i + 1) * H + 2 * lane];
            u64 w2 = *(const u64*)&sU2[(i + 2) * H + 2 * lane];
            u64 w3 = *(const u64*)&sU2[(i + 3) * H + 2 * lane];
#pragma unroll
            for (int j = 0; j < 4; j++) {
                float4 v = *(const float4*)&buf[j * 128 + i];
                fma2(Z[j], pack2(v.x), w0);
                fma2(Z[j], pack2(v.y), w1);
                fma2(Z[j], pack2(v.z), w2);
                fma2(Z[j], pack2(v.w), w3);
            }
        }
#pragma unroll
        for (int j = 0; j < 4; j++) {
            float2 zv = unpack_pair(Z[j]);
            *(float2*)&g_h[(base + j) * H + 2 * lane] =
                make_float2(fmaxf(zv.x, 0.f), fmaxf(zv.y, 0.f));
        }
        __syncwarp();
    }
}

// ---------------------------------------------------------------------------
__global__ void k_final(const int* __restrict__ n2g, float* __restrict__ out) {
    int wid = threadIdx.x >> 5, lane = threadIdx.x & 31;
    int nwarps = (blockDim.x >> 5) * gridDim.x;
    int gw = blockIdx.x * (blockDim.x >> 5) + wid;
    for (int n = gw; n < NN; n += nwarps) {
        int g = n2g[n];
        float2 hv = *(const float2*)&g_h[n * H + 2 * lane];
        red_add_v2(&out[g * H + 2 * lane], hv.x, hv.y);
        *(float2*)&out[NG * H + n * H + 2 * lane] = hv;
    }
}

// ---------------------------------------------------------------------------
extern "C" void kernel_launch(void* const* d_in, const int* in_sizes, int n_in,
                              void* d_out, int out_size) {
    const float* x        = (const float*)d_in[0];
    const int*   el       = (const int*)d_in[1];
    const int*   nstruct  = (const int*)d_in[2];
    const float* ef       = (const float*)d_in[3];
    const float* ew       = (const float*)d_in[4];
    const int*   n2g      = (const int*)d_in[5];
    const float* lin_w    = (const float*)d_in[7];
    const float* lin_b    = (const float*)d_in[8];
    const float* msg_w1   = (const float*)d_in[9];
    const float* msg_b1   = (const float*)d_in[10];
    const float* msg_w2   = (const float*)d_in[11];
    const float* msg_b2   = (const float*)d_in[12];
    const float* upd_w1   = (const float*)d_in[13];
    const float* upd_b1   = (const float*)d_in[14];
    const float* upd_w2   = (const float*)d_in[15];
    const float* upd_b2   = (const float*)d_in[16];
    float* out = (float*)d_out;

    static const size_t UPD_SMEM = (16576 + 8 * 512) * sizeof(float);
    cudaFuncSetAttribute(k_upd, cudaFuncAttributeMaxDynamicSharedMemorySize,
                         (int)UPD_SMEM);

    const int TPB = 256;
    const int NODE_BLOCKS = 1184;
    const int EDGE_BLOCKS = 1184;

    bool fork = g_sr.ok;
    cudaStream_t sc = fork ? g_sr.s2 : (cudaStream_t)0;

    if (fork) {
        cudaEventRecord(g_sr.ev_fork, 0);
        cudaStreamWaitEvent(sc, g_sr.ev_fork, 0);
    }

    // CSR build chain — forked stream (overlaps with h0 + layer-0 pq)
    k_zero<<<(NN + TPB - 1) / TPB, TPB, 0, sc>>>(out);
    k_deg<<<(NE + TPB - 1) / TPB, TPB, 0, sc>>>(el);
    k_scan_a<<<NSCANB, 256, 0, sc>>>();
    k_scan_b<<<1, 32, 0, sc>>>();
    k_scan_c<<<NSCANB, 256, 0, sc>>>();
    k_scatter<<<(NE + TPB - 1) / TPB, TPB, 0, sc>>>(el, ef, ew);
    if (fork) cudaEventRecord(g_sr.ev_join, sc);

    // Node-side work — main stream (independent of CSR chain)
    k_h0<<<NODE_BLOCKS, TPB>>>(x, lin_w, lin_b);
    k_pq<<<NODE_BLOCKS, TPB>>>(msg_w1, msg_b1, nstruct);

    if (fork) cudaStreamWaitEvent(0, g_sr.ev_join, 0);

    for (int l = 0; l < NL; l++) {
        const float* w1 = msg_w1 + (size_t)l * MSGIN * H;
        if (l > 0)
            k_pq<<<NODE_BLOCKS, TPB>>>(w1, msg_b1 + l * H, nstruct);
        k_edge_csr<<<EDGE_BLOCKS, TPB>>>(w1 + (2 * H + 2 * SCD) * H);
        k_upd<<<NODE_BLOCKS, TPB, UPD_SMEM>>>(
            msg_w2 + (size_t)l * H * H, msg_b2 + l * H,
            upd_w1 + (size_t)l * 2 * H * H, upd_b1 + l * H,
            upd_w2 + (size_t)l * H * H, upd_b2 + l * H);
    }

    k_final<<<NODE_BLOCKS, TPB>>>(n2g, out);
}

// round 13
// speedup vs baseline: 1.0507x; 1.0507x over previous
#include <cuda_runtime.h>
#include <cstdint>

#define NN     100000
#define NE     1600000
#define H      64
#define SCD    6
#define ED     16
#define NL     2
#define MSGIN  156
#define NG     128
#define NSCANB ((NN + 1023) / 1024)   // 98

typedef unsigned long long u64;

__device__ float g_h[NN * H];
__device__ float g_P[NN * H];
__device__ float g_Q[NN * H];
__device__ float g_S[NN * H];
__device__ float g_cnt[NN];
__device__ int   g_deg[NN];
__device__ int   g_off[NN + 1];
__device__ int   g_cur[NN];
__device__ int   g_bsum[NSCANB];
__device__ int2  g_cse[NE];            // (src, ew_bits) CSR-by-dst order
__device__ float g_efp[NE * ED + 32];  // edge_feature permuted to CSR order

// ---- f32x2 helpers (node GEMMs only) -------------------------------------
__device__ __forceinline__ u64 pack2(float x) {
    u64 r; asm("mov.b64 %0, {%1, %1};" : "=l"(r) : "f"(x)); return r;
}
__device__ __forceinline__ u64 pack_pair(float lo, float hi) {
    u64 r; asm("mov.b64 %0, {%1, %2};" : "=l"(r) : "f"(lo), "f"(hi)); return r;
}
__device__ __forceinline__ float2 unpack_pair(u64 v) {
    float2 f; asm("mov.b64 {%0, %1}, %2;" : "=f"(f.x), "=f"(f.y) : "l"(v)); return f;
}
__device__ __forceinline__ void fma2(u64& a, u64 b, u64 c) {
    asm("fma.rn.f32x2 %0, %1, %2, %0;" : "+l"(a) : "l"(b), "l"(c));
}
__device__ __forceinline__ void red_add_v2(float* p, float a, float b) {
    asm volatile("red.global.add.v2.f32 [%0], {%1, %2};"
                 :: "l"(p), "f"(a), "f"(b) : "memory");
}

// ---- fork/join stream resources (created at static init, pre-checkpoint) --
struct StreamRes {
    cudaStream_t s2 = nullptr;
    cudaEvent_t ev_fork = nullptr, ev_join = nullptr;
    bool ok = false;
    StreamRes() {
        if (cudaStreamCreateWithFlags(&s2, cudaStreamNonBlocking) != cudaSuccess) return;
        if (cudaEventCreateWithFlags(&ev_fork, cudaEventDisableTiming) != cudaSuccess) return;
        if (cudaEventCreateWithFlags(&ev_join, cudaEventDisableTiming) != cudaSuccess) return;
        ok = true;
    }
};
static StreamRes g_sr;

// ---------------------------------------------------------------------------
// CSR build chain
// ---------------------------------------------------------------------------
__global__ void k_zero(float* __restrict__ out) {
    int i = blockIdx.x * blockDim.x + threadIdx.x;
    if (i < NN) g_deg[i] = 0;
    if (i < NG * H) out[i] = 0.f;
}

__global__ void k_deg(const int* __restrict__ el) {
    int e = blockIdx.x * blockDim.x + threadIdx.x;
    if (e < NE) atomicAdd(&g_deg[el[2 * e + 1]], 1);
}

__global__ void k_scan_a() {
    __shared__ int wsum[8];
    int b = blockIdx.x, t = threadIdx.x, lane = t & 31, wid = t >> 5;
    int base = b * 1024 + t * 4;
    int s = 0;
#pragma unroll
    for (int j = 0; j < 4; j++) { int n = base + j; if (n < NN) s += g_deg[n]; }
#pragma unroll
    for (int d = 16; d > 0; d >>= 1) s += __shfl_down_sync(~0u, s, d);
    if (lane == 0) wsum[wid] = s;
    __syncthreads();
    if (t == 0) {
        int tot = 0;
#pragma unroll
        for (int w = 0; w < 8; w++) tot += wsum[w];
        g_bsum[b] = tot;
    }
}

__global__ void k_scan_b() {   // 1 warp
    int lane = threadIdx.x;
    int v[4];
    int base = lane * 4;
#pragma unroll
    for (int j = 0; j < 4; j++) v[j] = (base + j < NSCANB) ? g_bsum[base + j] : 0;
    int s = v[0] + v[1] + v[2] + v[3];
    int incl = s;
#pragma unroll
    for (int d = 1; d < 32; d <<= 1) {
        int x = __shfl_up_sync(~0u, incl, d);
        if (lane >= d) incl += x;
    }
    int off = incl - s;
#pragma unroll
    for (int j = 0; j < 4; j++) {
        if (base + j < NSCANB) g_bsum[base + j] = off;
        off += v[j];
    }
}

__global__ void k_scan_c() {
    __shared__ int warp_tot[8];
    __shared__ int warp_off[8];
    int b = blockIdx.x, t = threadIdx.x, lane = t & 31, wid = t >> 5;
    int base = b * 1024 + t * 4;
    int v0 = 0, v1 = 0, v2 = 0, v3 = 0;
    if (base + 0 < NN) v0 = g_deg[base + 0];
    if (base + 1 < NN) v1 = g_deg[base + 1];
    if (base + 2 < NN) v2 = g_deg[base + 2];
    if (base + 3 < NN) v3 = g_deg[base + 3];
    int s = v0 + v1 + v2 + v3;
    int incl = s;
#pragma unroll
    for (int d = 1; d < 32; d <<= 1) {
        int x = __shfl_up_sync(~0u, incl, d);
        if (lane >= d) incl += x;
    }
    if (lane == 31) warp_tot[wid] = incl;
    __syncthreads();
    if (wid == 0) {
        int wt = (lane < 8) ? warp_tot[lane] : 0;
        int wincl = wt;
#pragma unroll
        for (int d = 1; d < 8; d <<= 1) {
            int x = __shfl_up_sync(~0u, wincl, d);
            if (lane >= d) wincl += x;
        }
        if (lane < 8) warp_off[lane] = wincl - wt;
    }
    __syncthreads();
    int off = g_bsum[b] + warp_off[wid] + (incl - s);
    if (base + 0 < NN) { g_off[base + 0] = off; g_cur[base + 0] = off; } off += v0;
    if (base + 1 < NN) { g_off[base + 1] = off; g_cur[base + 1] = off; } off += v1;
    if (base + 2 < NN) { g_off[base + 2] = off; g_cur[base + 2] = off; } off += v2;
    if (base + 3 < NN) { g_off[base + 3] = off; g_cur[base + 3] = off; }
    if (b == 0 && t == 0) g_off[NN] = NE;
}

__global__ void k_scatter(const int* __restrict__ el, const float* __restrict__ ef,
                          const float* __restrict__ ew) {
    int e = blockIdx.x * blockDim.x + threadIdx.x;
    if (e < NE) {
        int2 sd = ((const int2*)el)[e];
        int pos = atomicAdd(&g_cur[sd.y], 1);
        g_cse[pos] = make_int2(sd.x, __float_as_int(ew[e]));
        const float4* s4 = (const float4*)&ef[(size_t)e * ED];
        float4* d4 = (float4*)&g_efp[(size_t)pos * ED];
        d4[0] = s4[0]; d4[1] = s4[1]; d4[2] = s4[2]; d4[3] = s4[3];
    }
}

// ---------------------------------------------------------------------------
// h0 = x @ lin_w + lin_b   — 4 nodes/warp, f32x2 (r9 version)
// ---------------------------------------------------------------------------
__global__ void k_h0(const float* __restrict__ x, const float* __restrict__ w,
                     const float* __restrict__ b) {
    __shared__ __align__(16) float sW[H * H];
    __shared__ float sB[H];
    __shared__ __align__(16) float sin_[8][4][H];
    for (int i = threadIdx.x; i < H * H; i += blockDim.x) sW[i] = w[i];
    for (int i = threadIdx.x; i < H; i += blockDim.x) sB[i] = b[i];
    __syncthreads();

    int wid = threadIdx.x >> 5, lane = threadIdx.x & 31;
    int nwarps = (blockDim.x >> 5) * gridDim.x;
    int gw = blockIdx.x * (blockDim.x >> 5) + wid;
    for (int t = gw; t < NN / 4; t += nwarps) {
        int base = t * 4;
#pragma unroll
        for (int j = 0; j < 4; j++) {
            float2 xv = *(const float2*)&x[(base + j) * H + 2 * lane];
            sin_[wid][j][2 * lane] = xv.x;
            sin_[wid][j][2 * lane + 1] = xv.y;
        }
        __syncwarp();
        u64 A[4];
        u64 bini = pack_pair(sB[2 * lane], sB[2 * lane + 1]);
#pragma unroll
        for (int j = 0; j < 4; j++) A[j] = bini;
#pragma unroll
        for (int i = 0; i < H; i += 4) {
            u64 w0 = *(const u64*)&sW[(i + 0) * H + 2 * lane];
            u64 w1 = *(const u64*)&sW[(i + 1) * H + 2 * lane];
            u64 w2 = *(const u64*)&sW[(i + 2) * H + 2 * lane];
            u64 w3 = *(const u64*)&sW[(i + 3) * H + 2 * lane];
#pragma unroll
            for (int j = 0; j < 4; j++) {
                float4 v = *(const float4*)&sin_[wid][j][i];
                fma2(A[j], pack2(v.x), w0);
                fma2(A[j], pack2(v.y), w1);
                fma2(A[j], pack2(v.z), w2);
                fma2(A[j], pack2(v.w), w3);
            }
        }
#pragma unroll
        for (int j = 0; j < 4; j++)
            *(float2*)&g_h[(base + j) * H + 2 * lane] = unpack_pair(A[j]);
        __syncwarp();
    }
}

// ---------------------------------------------------------------------------
// P = h@Wa + sc@Wc + b1 ; Q = h@Wb + sc@Wd   — 4 nodes/warp, f32x2 (r9)
// ---------------------------------------------------------------------------
__global__ void k_pq(const float* __restrict__ w1, const float* __restrict__ b1,
                     const int* __restrict__ nstruct) {
    __shared__ __align__(16) float sWP[(H + SCD) * H];
    __shared__ __align__(16) float sWQ[(H + SCD) * H];
    __shared__ float sB1[H];
    __shared__ __align__(16) float sin_[8][4][72];
    for (int i = threadIdx.x; i < H * H; i += blockDim.x) {
        sWP[i] = w1[i];
        sWQ[i] = w1[H * H + i];
    }
    for (int i = threadIdx.x; i < SCD * H; i += blockDim.x) {
        sWP[H * H + i] = w1[2 * H * H + i];
        sWQ[H * H + i] = w1[2 * H * H + SCD * H + i];
    }
    for (int i = threadIdx.x; i < H; i += blockDim.x) sB1[i] = b1[i];
    __syncthreads();

    int wid = threadIdx.x >> 5, lane = threadIdx.x & 31;
    int nwarps = (blockDim.x >> 5) * gridDim.x;
    int gw = blockIdx.x * (blockDim.x >> 5) + wid;
    for (int t = gw; t < NN / 4; t += nwarps) {
        int base = t * 4;
#pragma unroll
        for (int j = 0; j < 4; j++) {
            int n = base + j;
            float2 hv = *(const float2*)&g_h[n * H + 2 * lane];
            sin_[wid][j][2 * lane] = hv.x;
            sin_[wid][j][2 * lane + 1] = hv.y;
            if (lane < SCD) sin_[wid][j][H + lane] = (float)nstruct[n * SCD + lane];
        }
        __syncwarp();
        u64 P[4], Q[4];
        u64 bini = pack_pair(sB1[2 * lane], sB1[2 * lane + 1]);
#pragma unroll
        for (int j = 0; j < 4; j++) { P[j] = bini; Q[j] = 0ull; }
#pragma unroll 4
        for (int i = 0; i < H; i += 4) {
            u64 wp0 = *(const u64*)&sWP[(i + 0) * H + 2 * lane];
            u64 wp1 = *(const u64*)&sWP[(i + 1) * H + 2 * lane];
            u64 wp2 = *(const u64*)&sWP[(i + 2) * H + 2 * lane];
            u64 wp3 = *(const u64*)&sWP[(i + 3) * H + 2 * lane];
            u64 wq0 = *(const u64*)&sWQ[(i + 0) * H + 2 * lane];
            u64 wq1 = *(const u64*)&sWQ[(i + 1) * H + 2 * lane];
            u64 wq2 = *(const u64*)&sWQ[(i + 2) * H + 2 * lane];
            u64 wq3 = *(const u64*)&sWQ[(i + 3) * H + 2 * lane];
#pragma unroll
            for (int j = 0; j < 4; j++) {
                float4 v = *(const float4*)&sin_[wid][j][i];
                u64 v0 = pack2(v.x), v1 = pack2(v.y), v2 = pack2(v.z), v3 = pack2(v.w);
                fma2(P[j], v0, wp0); fma2(Q[j], v0, wq0);
                fma2(P[j], v1, wp1); fma2(Q[j], v1, wq1);
                fma2(P[j], v2, wp2); fma2(Q[j], v2, wq2);
                fma2(P[j], v3, wp3); fma2(Q[j], v3, wq3);
            }
        }
#pragma unroll
        for (int i = H; i < H + SCD; i++) {
            u64 wp = *(const u64*)&sWP[i * H + 2 * lane];
            u64 wq = *(const u64*)&sWQ[i * H + 2 * lane];
#pragma unroll
            for (int j = 0; j < 4; j++) {
                u64 vv = pack2(sin_[wid][j][i]);
                fma2(P[j], vv, wp);
                fma2(Q[j], vv, wq);
            }
        }
#pragma unroll
        for (int j = 0; j < 4; j++) {
            int n = base + j;
            *(float2*)&g_P[n * H + 2 * lane] = unpack_pair(P[j]);
            *(float2*)&g_Q[n * H + 2 * lane] = unpack_pair(Q[j]);
        }
        __syncwarp();
    }
}

// ---------------------------------------------------------------------------
// Edge pass: CSR by dst, warp per node. 4-edge mainloop with DOUBLE-BUFFERED
// smem ef staging: 2 STS + 16 broadcast LDS.128 replace 64 SHFLs per batch.
//   S[n] = sum ew * relu(P[src] + Q[n] + ef @ We) ;  cnt[n] = sum ew
// ---------------------------------------------------------------------------
__device__ __forceinline__ void edge_single(
    int k, int lane, float2 q, const float* wr0, const float* wr1,
    float& acc0, float& acc1, float& cw) {
    int2 s0 = g_cse[k];
    float myef = (lane < ED) ? g_efp[(size_t)k * ED + lane] : 0.f;
    float2 p0 = *(const float2*)&g_P[(size_t)s0.x * H + 2 * lane];
    float a00 = p0.x + q.x, a01 = p0.y + q.y;
#pragma unroll
    for (int i = 0; i < ED; i++) {
        float v0 = __shfl_sync(0xffffffffu, myef, i);
        a00 = fmaf(v0, wr0[i], a00);
        a01 = fmaf(v0, wr1[i], a01);
    }
    float w0 = __int_as_float(s0.y);
    acc0 = fmaf(fmaxf(a00, 0.f), w0, acc0);
    acc1 = fmaf(fmaxf(a01, 0.f), w0, acc1);
    cw += w0;
}

__global__ void __launch_bounds__(256) k_edge_csr(const float* __restrict__ We_g) {
    // per-warp double-buffered staging: [warp][parity][64]
    __shared__ __align__(16) float sef[8][2][64];
    int wid = threadIdx.x >> 5, lane = threadIdx.x & 31;
    float wr0[ED], wr1[ED];
#pragma unroll
    for (int i = 0; i < ED; i++) {
        float2 wv = *(const float2*)&We_g[i * H + 2 * lane];
        wr0[i] = wv.x; wr1[i] = wv.y;
    }
    // interleave slot: pos 2i = edge-A value i, pos 2i+1 = edge-B value i
    int slot = (lane < 16) ? 2 * lane : 2 * (lane - 16) + 1;
    float (*buf)[64] = sef[wid];

    int nwarps = (blockDim.x >> 5) * gridDim.x;
    int gw = blockIdx.x * (blockDim.x >> 5) + wid;
    for (int n = gw; n < NN; n += nwarps) {
        int row = g_off[n], end = g_off[n + 1];
        float2 q = *(const float2*)&g_Q[n * H + 2 * lane];
        float acc0 = 0.f, acc1 = 0.f, cw = 0.f;
        int k = row;
        if ((k & 1) && k < end) {                      // peel odd head → k even
            edge_single(k, lane, q, wr0, wr1, acc0, acc1, cw);
            k++;
        }
        int nb = (end - k) >> 2;                       // 4-edge batches
        if (nb > 0) {
            buf[0][slot]      = g_efp[(size_t)k * ED + lane];
            buf[0][32 + slot] = g_efp[(size_t)(k + 2) * ED + lane];
            __syncwarp();
            int p = 0;
            for (int b = 0; b < nb; b++) {
                int kk = k + b * 4;
                if (b + 1 < nb) {                      // stage next batch
                    int kn = kk + 4;
                    buf[p ^ 1][slot]      = g_efp[(size_t)kn * ED + lane];
                    buf[p ^ 1][32 + slot] = g_efp[(size_t)(kn + 2) * ED + lane];
                }
                int4 c01 = *(const int4*)&g_cse[kk];
                int4 c23 = *(const int4*)&g_cse[kk + 2];
                float2 p0 = *(const float2*)&g_P[(size_t)c01.x * H + 2 * lane];
                float2 p1 = *(const float2*)&g_P[(size_t)c01.z * H + 2 * lane];
                float2 p2 = *(const float2*)&g_P[(size_t)c23.x * H + 2 * lane];
                float2 p3 = *(const float2*)&g_P[(size_t)c23.z * H + 2 * lane];
                float a00 = p0.x + q.x, a01 = p0.y + q.y;
                float a10 = p1.x + q.x, a11 = p1.y + q.y;
                float a20 = p2.x + q.x, a21 = p2.y + q.y;
                float a30 = p3.x + q.x, a31 = p3.y + q.y;
#pragma unroll
                for (int m = 0; m < 8; m++) {
                    float4 vA = *(const float4*)&buf[p][4 * m];        // bcast
                    float4 vB = *(const float4*)&buf[p][32 + 4 * m];   // bcast
                    a00 = fmaf(vA.x, wr0[2 * m], a00);
                    a01 = fmaf(vA.x, wr1[2 * m], a01);
                    a10 = fmaf(vA.y, wr0[2 * m], a10);
                    a11 = fmaf(vA.y, wr1[2 * m], a11);
                    a00 = fmaf(vA.z, wr0[2 * m + 1], a00);
                    a01 = fmaf(vA.z, wr1[2 * m + 1], a01);
                    a10 = fmaf(vA.w, wr0[2 * m + 1], a10);
                    a11 = fmaf(vA.w, wr1[2 * m + 1], a11);
                    a20 = fmaf(vB.x, wr0[2 * m], a20);
                    a21 = fmaf(vB.x, wr1[2 * m], a21);
                    a30 = fmaf(vB.y, wr0[2 * m], a30);
                    a31 = fmaf(vB.y, wr1[2 * m], a31);
                    a20 = fmaf(vB.z, wr0[2 * m + 1], a20);
                    a21 = fmaf(vB.z, wr1[2 * m + 1], a21);
                    a30 = fmaf(vB.w, wr0[2 * m + 1], a30);
                    a31 = fmaf(vB.w, wr1[2 * m + 1], a31);
                }
                float w0 = __int_as_float(c01.y), w1 = __int_as_float(c01.w);
                float w2 = __int_as_float(c23.y), w3 = __int_as_float(c23.w);
                acc0 = fmaf(fmaxf(a00, 0.f), w0, acc0);
                acc1 = fmaf(fmaxf(a01, 0.f), w0, acc1);
                acc0 = fmaf(fmaxf(a10, 0.f), w1, acc0);
                acc1 = fmaf(fmaxf(a11, 0.f), w1, acc1);
                acc0 = fmaf(fmaxf(a20, 0.f), w2, acc0);
                acc1 = fmaf(fmaxf(a21, 0.f), w2, acc1);
                acc0 = fmaf(fmaxf(a30, 0.f), w3, acc0);
                acc1 = fmaf(fmaxf(a31, 0.f), w3, acc1);
                cw += (w0 + w1) + (w2 + w3);
                __syncwarp();
                p ^= 1;
            }
            k += nb * 4;
        }
        if (k + 2 <= end) {                            // 2-edge tail (shfl)
            int4 c01 = *(const int4*)&g_cse[k];
            float m0 = g_efp[(size_t)k * ED + lane];
            float2 p0 = *(const float2*)&g_P[(size_t)c01.x * H + 2 * lane];
            float2 p1 = *(const float2*)&g_P[(size_t)c01.z * H + 2 * lane];
            float a00 = p0.x + q.x, a01 = p0.y + q.y;
            float a10 = p1.x + q.x, a11 = p1.y + q.y;
#pragma unroll
            for (int i = 0; i < ED; i++) {
                float v0 = __shfl_sync(0xffffffffu, m0, i);
                float v1 = __shfl_sync(0xffffffffu, m0, ED + i);
                a00 = fmaf(v0, wr0[i], a00);
                a01 = fmaf(v0, wr1[i], a01);
                a10 = fmaf(v1, wr0[i], a10);
                a11 = fmaf(v1, wr1[i], a11);
            }
            float w0 = __int_as_float(c01.y), w1 = __int_as_float(c01.w);
            acc0 = fmaf(fmaxf(a00, 0.f), w0, acc0);
            acc1 = fmaf(fmaxf(a01, 0.f), w0, acc1);
            acc0 = fmaf(fmaxf(a10, 0.f), w1, acc0);
            acc1 = fmaf(fmaxf(a11, 0.f), w1, acc1);
            cw += w0 + w1;
            k += 2;
        }
        if (k < end)                                   // single tail
            edge_single(k, lane, q, wr0, wr1, acc0, acc1, cw);

        *(float2*)&g_S[n * H + 2 * lane] = make_float2(acc0, acc1);
        if (lane == 0) g_cnt[n] = cw;
    }
}

// ---------------------------------------------------------------------------
// upd = S@W2 + cnt*b2 ; t = relu([h,upd]@U1+ub1) ; h = relu(t@U2+ub2)  (r9)
// ---------------------------------------------------------------------------
__global__ void k_upd(const float* __restrict__ w2g, const float* __restrict__ b2,
                      const float* __restrict__ u1g, const float* __restrict__ ub1,
                      const float* __restrict__ u2g, const float* __restrict__ ub2) {
    extern __shared__ float sm[];
    float* sW2 = sm;
    float* sU1 = sm + 4096;
    float* sU2 = sm + 12288;
    float* sB2 = sm + 16384;
    float* sUB1 = sm + 16448;
    float* sUB2 = sm + 16512;
    float* sbuf = sm + 16576;

    for (int i = threadIdx.x; i < H * H; i += blockDim.x) { sW2[i] = w2g[i]; sU2[i] = u2g[i]; }
    for (int i = threadIdx.x; i < 2 * H * H; i += blockDim.x) sU1[i] = u1g[i];
    for (int i = threadIdx.x; i < H; i += blockDim.x) {
        sB2[i] = b2[i]; sUB1[i] = ub1[i]; sUB2[i] = ub2[i];
    }
    __syncthreads();

    int wid = threadIdx.x >> 5, lane = threadIdx.x & 31;
    float* buf = sbuf + wid * 512;
    int nwarps = (blockDim.x >> 5) * gridDim.x;
    int gw = blockIdx.x * (blockDim.x >> 5) + wid;
    for (int t = gw; t < NN / 4; t += nwarps) {
        int base = t * 4;
        float cnt[4];
#pragma unroll
        for (int j = 0; j < 4; j++) {
            int n = base + j;
            float2 sv = *(const float2*)&g_S[n * H + 2 * lane];
            buf[j * 128 + 2 * lane] = sv.x;
            buf[j * 128 + 2 * lane + 1] = sv.y;
            cnt[j] = g_cnt[n];
        }
        __syncwarp();
        float bb0 = sB2[2 * lane], bb1 = sB2[2 * lane + 1];
        u64 U[4];
#pragma unroll
        for (int j = 0; j < 4; j++) U[j] = pack_pair(cnt[j] * bb0, cnt[j] * bb1);
#pragma unroll 4
        for (int i = 0; i < H; i += 4) {
            u64 w0 = *(const u64*)&sW2[(i + 0) * H + 2 * lane];
            u64 w1 = *(const u64*)&sW2[(i + 1) * H + 2 * lane];
            u64 w2 = *(const u64*)&sW2[(i + 2) * H + 2 * lane];
            u64 w3 = *(const u64*)&sW2[(i + 3) * H + 2 * lane];
#pragma unroll
            for (int j = 0; j < 4; j++) {
                float4 v = *(const float4*)&buf[j * 128 + i];
                fma2(U[j], pack2(v.x), w0);
                fma2(U[j], pack2(v.y), w1);
                fma2(U[j], pack2(v.z), w2);
                fma2(U[j], pack2(v.w), w3);
            }
        }
        __syncwarp();
#pragma unroll
        for (int j = 0; j < 4; j++) {
            int n = base + j;
            float2 hv = *(const float2*)&g_h[n * H + 2 * lane];
            float2 uv = unpack_pair(U[j]);
            buf[j * 128 + 2 * lane] = hv.x;
            buf[j * 128 + 2 * lane + 1] = hv.y;
            buf[j * 128 + H + 2 * lane] = uv.x;
            buf[j * 128 + H + 2 * lane + 1] = uv.y;
        }
        __syncwarp();
        u64 T[4];
        u64 tb = pack_pair(sUB1[2 * lane], sUB1[2 * lane + 1]);
#pragma unroll
        for (int j = 0; j < 4; j++) T[j] = tb;
#pragma unroll 4
        for (int i = 0; i < 2 * H; i += 4) {
            u64 w0 = *(const u64*)&sU1[(i + 0) * H + 2 * lane];
            u64 w1 = *(const u64*)&sU1[(i + 1) * H + 2 * lane];
            u64 w2 = *(const u64*)&sU1[(i + 2) * H + 2 * lane];
            u64 w3 = *(const u64*)&sU1[(i + 3) * H + 2 * lane];
#pragma unroll
            for (int j = 0; j < 4; j++) {
                float4 v = *(const float4*)&buf[j * 128 + i];
                fma2(T[j], pack2(v.x), w0);
                fma2(T[j], pack2(v.y), w1);
                fma2(T[j], pack2(v.z), w2);
                fma2(T[j], pack2(v.w), w3);
            }
        }
        __syncwarp();
#pragma unroll
        for (int j = 0; j < 4; j++) {
            float2 tv = unpack_pair(T[j]);
            buf[j * 128 + 2 * lane] = fmaxf(tv.x, 0.f);
            buf[j * 128 + 2 * lane + 1] = fmaxf(tv.y, 0.f);
        }
        __syncwarp();
        u64 Z[4];
        u64 zb = pack_pair(sUB2[2 * lane], sUB2[2 * lane + 1]);
#pragma unroll
        for (int j = 0; j < 4; j++) Z[j] = zb;
#pragma unroll 4
        for (int i = 0; i < H; i += 4) {
            u64 w0 = *(const u64*)&sU2[(i + 0) * H + 2 * lane];
            u64 w1 = *(const u64*)&sU2[(i + 1) * H + 2 * lane];
            u64 w2 = *(const u64*)&sU2[(i + 2) * H + 2 * lane];
            u64 w3 = *(const u64*)&sU2[(i + 3) * H + 2 * lane];
#pragma unroll
            for (int j = 0; j < 4; j++) {
                float4 v = *(const float4*)&buf[j * 128 + i];
                fma2(Z[j], pack2(v.x), w0);
                fma2(Z[j], pack2(v.y), w1);
                fma2(Z[j], pack2(v.z), w2);
                fma2(Z[j], pack2(v.w), w3);
            }
        }
#pragma unroll
        for (int j = 0; j < 4; j++) {
            float2 zv = unpack_pair(Z[j]);
            *(float2*)&g_h[(base + j) * H + 2 * lane] =
                make_float2(fmaxf(zv.x, 0.f), fmaxf(zv.y, 0.f));
        }
        __syncwarp();
    }
}

// ---------------------------------------------------------------------------
__global__ void k_final(const int* __restrict__ n2g, float* __restrict__ out) {
    int wid = threadIdx.x >> 5, lane = threadIdx.x & 31;
    int nwarps = (blockDim.x >> 5) * gridDim.x;
    int gw = blockIdx.x * (blockDim.x >> 5) + wid;
    for (int n = gw; n < NN; n += nwarps) {
        int g = n2g[n];
        float2 hv = *(const float2*)&g_h[n * H + 2 * lane];
        red_add_v2(&out[g * H + 2 * lane], hv.x, hv.y);
        *(float2*)&out[NG * H + n * H + 2 * lane] = hv;
    }
}

// ---------------------------------------------------------------------------
extern "C" void kernel_launch(void* const* d_in, const int* in_sizes, int n_in,
                              void* d_out, int out_size) {
    const float* x        = (const float*)d_in[0];
    const int*   el       = (const int*)d_in[1];
    const int*   nstruct  = (const int*)d_in[2];
    const float* ef       = (const float*)d_in[3];
    const float* ew       = (const float*)d_in[4];
    const int*   n2g      = (const int*)d_in[5];
    const float* lin_w    = (const float*)d_in[7];
    const float* lin_b    = (const float*)d_in[8];
    const float* msg_w1   = (const float*)d_in[9];
    const float* msg_b1   = (const float*)d_in[10];
    const float* msg_w2   = (const float*)d_in[11];
    const float* msg_b2   = (const float*)d_in[12];
    const float* upd_w1   = (const float*)d_in[13];
    const float* upd_b1   = (const float*)d_in[14];
    const float* upd_w2   = (const float*)d_in[15];
    const float* upd_b2   = (const float*)d_in[16];
    float* out = (float*)d_out;

    static const size_t UPD_SMEM = (16576 + 8 * 512) * sizeof(float);
    cudaFuncSetAttribute(k_upd, cudaFuncAttributeMaxDynamicSharedMemorySize,
                         (int)UPD_SMEM);

    const int TPB = 256;
    const int NODE_BLOCKS = 1184;
    const int EDGE_BLOCKS = 1184;

    bool fork = g_sr.ok;
    cudaStream_t sc = fork ? g_sr.s2 : (cudaStream_t)0;

    if (fork) {
        cudaEventRecord(g_sr.ev_fork, 0);
        cudaStreamWaitEvent(sc, g_sr.ev_fork, 0);
    }

    // CSR build chain — forked stream (overlaps with h0 + layer-0 pq)
    k_zero<<<(NN + TPB - 1) / TPB, TPB, 0, sc>>>(out);
    k_deg<<<(NE + TPB - 1) / TPB, TPB, 0, sc>>>(el);
    k_scan_a<<<NSCANB, 256, 0, sc>>>();
    k_scan_b<<<1, 32, 0, sc>>>();
    k_scan_c<<<NSCANB, 256, 0, sc>>>();
    k_scatter<<<(NE + TPB - 1) / TPB, TPB, 0, sc>>>(el, ef, ew);
    if (fork) cudaEventRecord(g_sr.ev_join, sc);

    // Node-side work — main stream (independent of CSR chain)
    k_h0<<<NODE_BLOCKS, TPB>>>(x, lin_w, lin_b);
    k_pq<<<NODE_BLOCKS, TPB>>>(msg_w1, msg_b1, nstruct);

    if (fork) cudaStreamWaitEvent(0, g_sr.ev_join, 0);

    for (int l = 0; l < NL; l++) {
        const float* w1 = msg_w1 + (size_t)l * MSGIN * H;
        if (l > 0)
            k_pq<<<NODE_BLOCKS, TPB>>>(w1, msg_b1 + l * H, nstruct);
        k_edge_csr<<<EDGE_BLOCKS, TPB>>>(w1 + (2 * H + 2 * SCD) * H);
        k_upd<<<NODE_BLOCKS, TPB, UPD_SMEM>>>(
            msg_w2 + (size_t)l * H * H, msg_b2 + l * H,
            upd_w1 + (size_t)l * 2 * H * H, upd_b1 + l * H,
            upd_w2 + (size_t)l * H * H, upd_b2 + l * H);
    }

    k_final<<<NODE_BLOCKS, TPB>>>(n2g, out);
}

// round 14
// speedup vs baseline: 1.0594x; 1.0082x over previous
#include <cuda_runtime.h>
#include <cstdint>

#define NN     100000
#define NE     1600000
#define H      64
#define SCD    6
#define ED     16
#define NL     2
#define MSGIN  156
#define NG     128
#define NSCANB ((NN + 1023) / 1024)   // 98

typedef unsigned long long u64;

__device__ float g_h[NN * H];
__device__ float g_P[NN * H];
__device__ float g_Q[NN * H];
__device__ float g_S[NN * H];
__device__ float g_cnt[NN];
__device__ int   g_deg[NN];
__device__ int   g_off[NN + 1];
__device__ int   g_cur[NN];
__device__ int   g_bsum[NSCANB];
__device__ int2  g_cse[NE];            // (src, ew_bits) CSR-by-dst order
__device__ float g_efp[NE * ED + 32];  // edge_feature permuted to CSR order

// ---- f32x2 helpers (node GEMMs only) -------------------------------------
__device__ __forceinline__ u64 pack2(float x) {
    u64 r; asm("mov.b64 %0, {%1, %1};" : "=l"(r) : "f"(x)); return r;
}
__device__ __forceinline__ u64 pack_pair(float lo, float hi) {
    u64 r; asm("mov.b64 %0, {%1, %2};" : "=l"(r) : "f"(lo), "f"(hi)); return r;
}
__device__ __forceinline__ float2 unpack_pair(u64 v) {
    float2 f; asm("mov.b64 {%0, %1}, %2;" : "=f"(f.x), "=f"(f.y) : "l"(v)); return f;
}
__device__ __forceinline__ void fma2(u64& a, u64 b, u64 c) {
    asm("fma.rn.f32x2 %0, %1, %2, %0;" : "+l"(a) : "l"(b), "l"(c));
}
__device__ __forceinline__ void red_add_v2(float* p, float a, float b) {
    asm volatile("red.global.add.v2.f32 [%0], {%1, %2};"
                 :: "l"(p), "f"(a), "f"(b) : "memory");
}

// ---- fork/join stream resources (created at static init, pre-checkpoint) --
struct StreamRes {
    cudaStream_t s2 = nullptr;
    cudaEvent_t ev_fork = nullptr, ev_join = nullptr;
    bool ok = false;
    StreamRes() {
        if (cudaStreamCreateWithFlags(&s2, cudaStreamNonBlocking) != cudaSuccess) return;
        if (cudaEventCreateWithFlags(&ev_fork, cudaEventDisableTiming) != cudaSuccess) return;
        if (cudaEventCreateWithFlags(&ev_join, cudaEventDisableTiming) != cudaSuccess) return;
        ok = true;
    }
};
static StreamRes g_sr;

// ---------------------------------------------------------------------------
// CSR build chain
// ---------------------------------------------------------------------------
__global__ void k_zero(float* __restrict__ out) {
    int i = blockIdx.x * blockDim.x + threadIdx.x;
    if (i < NN) g_deg[i] = 0;
    if (i < NG * H) out[i] = 0.f;
}

__global__ void k_deg(const int* __restrict__ el) {
    int e = blockIdx.x * blockDim.x + threadIdx.x;
    if (e < NE) atomicAdd(&g_deg[el[2 * e + 1]], 1);
}

__global__ void k_scan_a() {
    __shared__ int wsum[8];
    int b = blockIdx.x, t = threadIdx.x, lane = t & 31, wid = t >> 5;
    int base = b * 1024 + t * 4;
    int s = 0;
#pragma unroll
    for (int j = 0; j < 4; j++) { int n = base + j; if (n < NN) s += g_deg[n]; }
#pragma unroll
    for (int d = 16; d > 0; d >>= 1) s += __shfl_down_sync(~0u, s, d);
    if (lane == 0) wsum[wid] = s;
    __syncthreads();
    if (t == 0) {
        int tot = 0;
#pragma unroll
        for (int w = 0; w < 8; w++) tot += wsum[w];
        g_bsum[b] = tot;
    }
}

__global__ void k_scan_b() {   // 1 warp
    int lane = threadIdx.x;
    int v[4];
    int base = lane * 4;
#pragma unroll
    for (int j = 0; j < 4; j++) v[j] = (base + j < NSCANB) ? g_bsum[base + j] : 0;
    int s = v[0] + v[1] + v[2] + v[3];
    int incl = s;
#pragma unroll
    for (int d = 1; d < 32; d <<= 1) {
        int x = __shfl_up_sync(~0u, incl, d);
        if (lane >= d) incl += x;
    }
    int off = incl - s;
#pragma unroll
    for (int j = 0; j < 4; j++) {
        if (base + j < NSCANB) g_bsum[base + j] = off;
        off += v[j];
    }
}

__global__ void k_scan_c() {
    __shared__ int warp_tot[8];
    __shared__ int warp_off[8];
    int b = blockIdx.x, t = threadIdx.x, lane = t & 31, wid = t >> 5;
    int base = b * 1024 + t * 4;
    int v0 = 0, v1 = 0, v2 = 0, v3 = 0;
    if (base + 0 < NN) v0 = g_deg[base + 0];
    if (base + 1 < NN) v1 = g_deg[base + 1];
    if (base + 2 < NN) v2 = g_deg[base + 2];
    if (base + 3 < NN) v3 = g_deg[base + 3];
    int s = v0 + v1 + v2 + v3;
    int incl = s;
#pragma unroll
    for (int d = 1; d < 32; d <<= 1) {
        int x = __shfl_up_sync(~0u, incl, d);
        if (lane >= d) incl += x;
    }
    if (lane == 31) warp_tot[wid] = incl;
    __syncthreads();
    if (wid == 0) {
        int wt = (lane < 8) ? warp_tot[lane] : 0;
        int wincl = wt;
#pragma unroll
        for (int d = 1; d < 8; d <<= 1) {
            int x = __shfl_up_sync(~0u, wincl, d);
            if (lane >= d) wincl += x;
        }
        if (lane < 8) warp_off[lane] = wincl - wt;
    }
    __syncthreads();
    int off = g_bsum[b] + warp_off[wid] + (incl - s);
    if (base + 0 < NN) { g_off[base + 0] = off; g_cur[base + 0] = off; } off += v0;
    if (base + 1 < NN) { g_off[base + 1] = off; g_cur[base + 1] = off; } off += v1;
    if (base + 2 < NN) { g_off[base + 2] = off; g_cur[base + 2] = off; } off += v2;
    if (base + 3 < NN) { g_off[base + 3] = off; g_cur[base + 3] = off; }
    if (b == 0 && t == 0) g_off[NN] = NE;
}

__global__ void k_scatter(const int* __restrict__ el, const float* __restrict__ ef,
                          const float* __restrict__ ew) {
    int e = blockIdx.x * blockDim.x + threadIdx.x;
    if (e < NE) {
        int2 sd = ((const int2*)el)[e];
        int pos = atomicAdd(&g_cur[sd.y], 1);
        g_cse[pos] = make_int2(sd.x, __float_as_int(ew[e]));
        const float4* s4 = (const float4*)&ef[(size_t)e * ED];
        float4* d4 = (float4*)&g_efp[(size_t)pos * ED];
        d4[0] = s4[0]; d4[1] = s4[1]; d4[2] = s4[2]; d4[3] = s4[3];
    }
}

// ---------------------------------------------------------------------------
// h0 = x @ lin_w + lin_b   — 4 nodes/warp, f32x2 (r9 version)
// ---------------------------------------------------------------------------
__global__ void k_h0(const float* __restrict__ x, const float* __restrict__ w,
                     const float* __restrict__ b) {
    __shared__ __align__(16) float sW[H * H];
    __shared__ float sB[H];
    __shared__ __align__(16) float sin_[8][4][H];
    for (int i = threadIdx.x; i < H * H; i += blockDim.x) sW[i] = w[i];
    for (int i = threadIdx.x; i < H; i += blockDim.x) sB[i] = b[i];
    __syncthreads();

    int wid = threadIdx.x >> 5, lane = threadIdx.x & 31;
    int nwarps = (blockDim.x >> 5) * gridDim.x;
    int gw = blockIdx.x * (blockDim.x >> 5) + wid;
    for (int t = gw; t < NN / 4; t += nwarps) {
        int base = t * 4;
#pragma unroll
        for (int j = 0; j < 4; j++) {
            float2 xv = *(const float2*)&x[(base + j) * H + 2 * lane];
            sin_[wid][j][2 * lane] = xv.x;
            sin_[wid][j][2 * lane + 1] = xv.y;
        }
        __syncwarp();
        u64 A[4];
        u64 bini = pack_pair(sB[2 * lane], sB[2 * lane + 1]);
#pragma unroll
        for (int j = 0; j < 4; j++) A[j] = bini;
#pragma unroll
        for (int i = 0; i < H; i += 4) {
            u64 w0 = *(const u64*)&sW[(i + 0) * H + 2 * lane];
            u64 w1 = *(const u64*)&sW[(i + 1) * H + 2 * lane];
            u64 w2 = *(const u64*)&sW[(i + 2) * H + 2 * lane];
            u64 w3 = *(const u64*)&sW[(i + 3) * H + 2 * lane];
#pragma unroll
            for (int j = 0; j < 4; j++) {
                float4 v = *(const float4*)&sin_[wid][j][i];
                fma2(A[j], pack2(v.x), w0);
                fma2(A[j], pack2(v.y), w1);
                fma2(A[j], pack2(v.z), w2);
                fma2(A[j], pack2(v.w), w3);
            }
        }
#pragma unroll
        for (int j = 0; j < 4; j++)
            *(float2*)&g_h[(base + j) * H + 2 * lane] = unpack_pair(A[j]);
        __syncwarp();
    }
}

// ---------------------------------------------------------------------------
// P = h@Wa + sc@Wc + b1 ; Q = h@Wb + sc@Wd   — 4 nodes/warp, f32x2 (r9)
// ---------------------------------------------------------------------------
__global__ void k_pq(const float* __restrict__ w1, const float* __restrict__ b1,
                     const int* __restrict__ nstruct) {
    __shared__ __align__(16) float sWP[(H + SCD) * H];
    __shared__ __align__(16) float sWQ[(H + SCD) * H];
    __shared__ float sB1[H];
    __shared__ __align__(16) float sin_[8][4][72];
    for (int i = threadIdx.x; i < H * H; i += blockDim.x) {
        sWP[i] = w1[i];
        sWQ[i] = w1[H * H + i];
    }
    for (int i = threadIdx.x; i < SCD * H; i += blockDim.x) {
        sWP[H * H + i] = w1[2 * H * H + i];
        sWQ[H * H + i] = w1[2 * H * H + SCD * H + i];
    }
    for (int i = threadIdx.x; i < H; i += blockDim.x) sB1[i] = b1[i];
    __syncthreads();

    int wid = threadIdx.x >> 5, lane = threadIdx.x & 31;
    int nwarps = (blockDim.x >> 5) * gridDim.x;
    int gw = blockIdx.x * (blockDim.x >> 5) + wid;
    for (int t = gw; t < NN / 4; t += nwarps) {
        int base = t * 4;
#pragma unroll
        for (int j = 0; j < 4; j++) {
            int n = base + j;
            float2 hv = *(const float2*)&g_h[n * H + 2 * lane];
            sin_[wid][j][2 * lane] = hv.x;
            sin_[wid][j][2 * lane + 1] = hv.y;
            if (lane < SCD) sin_[wid][j][H + lane] = (float)nstruct[n * SCD + lane];
        }
        __syncwarp();
        u64 P[4], Q[4];
        u64 bini = pack_pair(sB1[2 * lane], sB1[2 * lane + 1]);
#pragma unroll
        for (int j = 0; j < 4; j++) { P[j] = bini; Q[j] = 0ull; }
#pragma unroll 4
        for (int i = 0; i < H; i += 4) {
            u64 wp0 = *(const u64*)&sWP[(i + 0) * H + 2 * lane];
            u64 wp1 = *(const u64*)&sWP[(i + 1) * H + 2 * lane];
            u64 wp2 = *(const u64*)&sWP[(i + 2) * H + 2 * lane];
            u64 wp3 = *(const u64*)&sWP[(i + 3) * H + 2 * lane];
            u64 wq0 = *(const u64*)&sWQ[(i + 0) * H + 2 * lane];
            u64 wq1 = *(const u64*)&sWQ[(i + 1) * H + 2 * lane];
            u64 wq2 = *(const u64*)&sWQ[(i + 2) * H + 2 * lane];
            u64 wq3 = *(const u64*)&sWQ[(i + 3) * H + 2 * lane];
#pragma unroll
            for (int j = 0; j < 4; j++) {
                float4 v = *(const float4*)&sin_[wid][j][i];
                u64 v0 = pack2(v.x), v1 = pack2(v.y), v2 = pack2(v.z), v3 = pack2(v.w);
                fma2(P[j], v0, wp0); fma2(Q[j], v0, wq0);
                fma2(P[j], v1, wp1); fma2(Q[j], v1, wq1);
                fma2(P[j], v2, wp2); fma2(Q[j], v2, wq2);
                fma2(P[j], v3, wp3); fma2(Q[j], v3, wq3);
            }
        }
#pragma unroll
        for (int i = H; i < H + SCD; i++) {
            u64 wp = *(const u64*)&sWP[i * H + 2 * lane];
            u64 wq = *(const u64*)&sWQ[i * H + 2 * lane];
#pragma unroll
            for (int j = 0; j < 4; j++) {
                u64 vv = pack2(sin_[wid][j][i]);
                fma2(P[j], vv, wp);
                fma2(Q[j], vv, wq);
            }
        }
#pragma unroll
        for (int j = 0; j < 4; j++) {
            int n = base + j;
            *(float2*)&g_P[n * H + 2 * lane] = unpack_pair(P[j]);
            *(float2*)&g_Q[n * H + 2 * lane] = unpack_pair(Q[j]);
        }
        __syncwarp();
    }
}

// ---------------------------------------------------------------------------
// Edge pass: CSR by dst, warp per node. 8-edge staged batches (4 STS + 1
// syncwarp per 8 edges), computed as two 4-edge halves of broadcast LDS.128.
//   S[n] = sum ew * relu(P[src] + Q[n] + ef @ We) ;  cnt[n] = sum ew
// ---------------------------------------------------------------------------
__device__ __forceinline__ void edge_single(
    int k, int lane, float2 q, const float* wr0, const float* wr1,
    float& acc0, float& acc1, float& cw) {
    int2 s0 = g_cse[k];
    float myef = (lane < ED) ? g_efp[(size_t)k * ED + lane] : 0.f;
    float2 p0 = *(const float2*)&g_P[(size_t)s0.x * H + 2 * lane];
    float a00 = p0.x + q.x, a01 = p0.y + q.y;
#pragma unroll
    for (int i = 0; i < ED; i++) {
        float v0 = __shfl_sync(0xffffffffu, myef, i);
        a00 = fmaf(v0, wr0[i], a00);
        a01 = fmaf(v0, wr1[i], a01);
    }
    float w0 = __int_as_float(s0.y);
    acc0 = fmaf(fmaxf(a00, 0.f), w0, acc0);
    acc1 = fmaf(fmaxf(a01, 0.f), w0, acc1);
    cw += w0;
}

// compute 4 edges starting at kk using staged interleaved ef chunk cb[0..63]
__device__ __forceinline__ void compute4_staged(
    int kk, int lane, float2 q, const float* __restrict__ cb,
    const float* wr0, const float* wr1,
    float& acc0, float& acc1, float& cw) {
    int4 c01 = *(const int4*)&g_cse[kk];
    int4 c23 = *(const int4*)&g_cse[kk + 2];
    float2 p0 = *(const float2*)&g_P[(size_t)c01.x * H + 2 * lane];
    float2 p1 = *(const float2*)&g_P[(size_t)c01.z * H + 2 * lane];
    float2 p2 = *(const float2*)&g_P[(size_t)c23.x * H + 2 * lane];
    float2 p3 = *(const float2*)&g_P[(size_t)c23.z * H + 2 * lane];
    float a00 = p0.x + q.x, a01 = p0.y + q.y;
    float a10 = p1.x + q.x, a11 = p1.y + q.y;
    float a20 = p2.x + q.x, a21 = p2.y + q.y;
    float a30 = p3.x + q.x, a31 = p3.y + q.y;
#pragma unroll
    for (int m = 0; m < 8; m++) {
        float4 vA = *(const float4*)&cb[4 * m];        // bcast LDS.128
        float4 vB = *(const float4*)&cb[32 + 4 * m];   // bcast LDS.128
        a00 = fmaf(vA.x, wr0[2 * m], a00);
        a01 = fmaf(vA.x, wr1[2 * m], a01);
        a10 = fmaf(vA.y, wr0[2 * m], a10);
        a11 = fmaf(vA.y, wr1[2 * m], a11);
        a00 = fmaf(vA.z, wr0[2 * m + 1], a00);
        a01 = fmaf(vA.z, wr1[2 * m + 1], a01);
        a10 = fmaf(vA.w, wr0[2 * m + 1], a10);
        a11 = fmaf(vA.w, wr1[2 * m + 1], a11);
        a20 = fmaf(vB.x, wr0[2 * m], a20);
        a21 = fmaf(vB.x, wr1[2 * m], a21);
        a30 = fmaf(vB.y, wr0[2 * m], a30);
        a31 = fmaf(vB.y, wr1[2 * m], a31);
        a20 = fmaf(vB.z, wr0[2 * m + 1], a20);
        a21 = fmaf(vB.z, wr1[2 * m + 1], a21);
        a30 = fmaf(vB.w, wr0[2 * m + 1], a30);
        a31 = fmaf(vB.w, wr1[2 * m + 1], a31);
    }
    float w0 = __int_as_float(c01.y), w1 = __int_as_float(c01.w);
    float w2 = __int_as_float(c23.y), w3 = __int_as_float(c23.w);
    acc0 = fmaf(fmaxf(a00, 0.f), w0, acc0);
    acc1 = fmaf(fmaxf(a01, 0.f), w0, acc1);
    acc0 = fmaf(fmaxf(a10, 0.f), w1, acc0);
    acc1 = fmaf(fmaxf(a11, 0.f), w1, acc1);
    acc0 = fmaf(fmaxf(a20, 0.f), w2, acc0);
    acc1 = fmaf(fmaxf(a21, 0.f), w2, acc1);
    acc0 = fmaf(fmaxf(a30, 0.f), w3, acc0);
    acc1 = fmaf(fmaxf(a31, 0.f), w3, acc1);
    cw += (w0 + w1) + (w2 + w3);
}

__global__ void __launch_bounds__(256) k_edge_csr(const float* __restrict__ We_g) {
    // per-warp double-buffered staging: [warp][parity][128] (4 chunks of 32)
    __shared__ __align__(16) float sef[8][2][128];
    int wid = threadIdx.x >> 5, lane = threadIdx.x & 31;
    float wr0[ED], wr1[ED];
#pragma unroll
    for (int i = 0; i < ED; i++) {
        float2 wv = *(const float2*)&We_g[i * H + 2 * lane];
        wr0[i] = wv.x; wr1[i] = wv.y;
    }
    // interleave slot: pos 2i = edge-A value i, pos 2i+1 = edge-B value i
    int slot = (lane < 16) ? 2 * lane : 2 * (lane - 16) + 1;
    float (*buf)[128] = sef[wid];

    int nwarps = (blockDim.x >> 5) * gridDim.x;
    int gw = blockIdx.x * (blockDim.x >> 5) + wid;
    for (int n = gw; n < NN; n += nwarps) {
        int row = g_off[n], end = g_off[n + 1];
        float2 q = *(const float2*)&g_Q[n * H + 2 * lane];
        float acc0 = 0.f, acc1 = 0.f, cw = 0.f;
        int k = row;
        if ((k & 1) && k < end) {                      // peel odd head → k even
            edge_single(k, lane, q, wr0, wr1, acc0, acc1, cw);
            k++;
        }
        int nb = (end - k) >> 3;                       // 8-edge batches
        if (nb > 0) {
#pragma unroll
            for (int c = 0; c < 4; c++)
                buf[0][c * 32 + slot] = g_efp[(size_t)(k + 2 * c) * ED + lane];
            __syncwarp();
            int p = 0;
            for (int b = 0; b < nb; b++) {
                int kk = k + b * 8;
                if (b + 1 < nb) {                      // stage next batch
                    int kn = kk + 8;
#pragma unroll
                    for (int c = 0; c < 4; c++)
                        buf[p ^ 1][c * 32 + slot] =
                            g_efp[(size_t)(kn + 2 * c) * ED + lane];
                }
                compute4_staged(kk, lane, q, &buf[p][0], wr0, wr1, acc0, acc1, cw);
                compute4_staged(kk + 4, lane, q, &buf[p][64], wr0, wr1, acc0, acc1, cw);
                __syncwarp();
                p ^= 1;
            }
            k += nb * 8;
        }
        while (k + 2 <= end) {                         // 2-edge tail (shfl)
            int4 c01 = *(const int4*)&g_cse[k];
            float m0 = g_efp[(size_t)k * ED + lane];
            float2 p0 = *(const float2*)&g_P[(size_t)c01.x * H + 2 * lane];
            float2 p1 = *(const float2*)&g_P[(size_t)c01.z * H + 2 * lane];
            float a00 = p0.x + q.x, a01 = p0.y + q.y;
            float a10 = p1.x + q.x, a11 = p1.y + q.y;
#pragma unroll
            for (int i = 0; i < ED; i++) {
                float v0 = __shfl_sync(0xffffffffu, m0, i);
                float v1 = __shfl_sync(0xffffffffu, m0, ED + i);
                a00 = fmaf(v0, wr0[i], a00);
                a01 = fmaf(v0, wr1[i], a01);
                a10 = fmaf(v1, wr0[i], a10);
                a11 = fmaf(v1, wr1[i], a11);
            }
            float w0 = __int_as_float(c01.y), w1 = __int_as_float(c01.w);
            acc0 = fmaf(fmaxf(a00, 0.f), w0, acc0);
            acc1 = fmaf(fmaxf(a01, 0.f), w0, acc1);
            acc0 = fmaf(fmaxf(a10, 0.f), w1, acc0);
            acc1 = fmaf(fmaxf(a11, 0.f), w1, acc1);
            cw += w0 + w1;
            k += 2;
        }
        if (k < end)                                   // single tail
            edge_single(k, lane, q, wr0, wr1, acc0, acc1, cw);

        *(float2*)&g_S[n * H + 2 * lane] = make_float2(acc0, acc1);
        if (lane == 0) g_cnt[n] = cw;
    }
}

// ---------------------------------------------------------------------------
// upd = S@W2 + cnt*b2 ; t = relu([h,upd]@U1+ub1) ; h = relu(t@U2+ub2)  (r9)
// ---------------------------------------------------------------------------
__global__ void k_upd(const float* __restrict__ w2g, const float* __restrict__ b2,
                      const float* __restrict__ u1g, const float* __restrict__ ub1,
                      const float* __restrict__ u2g, const float* __restrict__ ub2) {
    extern __shared__ float sm[];
    float* sW2 = sm;
    float* sU1 = sm + 4096;
    float* sU2 = sm + 12288;
    float* sB2 = sm + 16384;
    float* sUB1 = sm + 16448;
    float* sUB2 = sm + 16512;
    float* sbuf = sm + 16576;

    for (int i = threadIdx.x; i < H * H; i += blockDim.x) { sW2[i] = w2g[i]; sU2[i] = u2g[i]; }
    for (int i = threadIdx.x; i < 2 * H * H; i += blockDim.x) sU1[i] = u1g[i];
    for (int i = threadIdx.x; i < H; i += blockDim.x) {
        sB2[i] = b2[i]; sUB1[i] = ub1[i]; sUB2[i] = ub2[i];
    }
    __syncthreads();

    int wid = threadIdx.x >> 5, lane = threadIdx.x & 31;
    float* buf = sbuf + wid * 512;
    int nwarps = (blockDim.x >> 5) * gridDim.x;
    int gw = blockIdx.x * (blockDim.x >> 5) + wid;
    for (int t = gw; t < NN / 4; t += nwarps) {
        int base = t * 4;
        float cnt[4];
#pragma unroll
        for (int j = 0; j < 4; j++) {
            int n = base + j;
            float2 sv = *(const float2*)&g_S[n * H + 2 * lane];
            buf[j * 128 + 2 * lane] = sv.x;
            buf[j * 128 + 2 * lane + 1] = sv.y;
            cnt[j] = g_cnt[n];
        }
        __syncwarp();
        float bb0 = sB2[2 * lane], bb1 = sB2[2 * lane + 1];
        u64 U[4];
#pragma unroll
        for (int j = 0; j < 4; j++) U[j] = pack_pair(cnt[j] * bb0, cnt[j] * bb1);
#pragma unroll 4
        for (int i = 0; i < H; i += 4) {
            u64 w0 = *(const u64*)&sW2[(i + 0) * H + 2 * lane];
            u64 w1 = *(const u64*)&sW2[(i + 1) * H + 2 * lane];
            u64 w2 = *(const u64*)&sW2[(i + 2) * H + 2 * lane];
            u64 w3 = *(const u64*)&sW2[(i + 3) * H + 2 * lane];
#pragma unroll
            for (int j = 0; j < 4; j++) {
                float4 v = *(const float4*)&buf[j * 128 + i];
                fma2(U[j], pack2(v.x), w0);
                fma2(U[j], pack2(v.y), w1);
                fma2(U[j], pack2(v.z), w2);
                fma2(U[j], pack2(v.w), w3);
            }
        }
        __syncwarp();
#pragma unroll
        for (int j = 0; j < 4; j++) {
            int n = base + j;
            float2 hv = *(const float2*)&g_h[n * H + 2 * lane];
            float2 uv = unpack_pair(U[j]);
            buf[j * 128 + 2 * lane] = hv.x;
            buf[j * 128 + 2 * lane + 1] = hv.y;
            buf[j * 128 + H + 2 * lane] = uv.x;
            buf[j * 128 + H + 2 * lane + 1] = uv.y;
        }
        __syncwarp();
        u64 T[4];
        u64 tb = pack_pair(sUB1[2 * lane], sUB1[2 * lane + 1]);
#pragma unroll
        for (int j = 0; j < 4; j++) T[j] = tb;
#pragma unroll 4
        for (int i = 0; i < 2 * H; i += 4) {
            u64 w0 = *(const u64*)&sU1[(i + 0) * H + 2 * lane];
            u64 w1 = *(const u64*)&sU1[(i + 1) * H + 2 * lane];
            u64 w2 = *(const u64*)&sU1[(i + 2) * H + 2 * lane];
            u64 w3 = *(const u64*)&sU1[(i + 3) * H + 2 * lane];
#pragma unroll
            for (int j = 0; j < 4; j++) {
                float4 v = *(const float4*)&buf[j * 128 + i];
                fma2(T[j], pack2(v.x), w0);
                fma2(T[j], pack2(v.y), w1);
                fma2(T[j], pack2(v.z), w2);
                fma2(T[j], pack2(v.w), w3);
            }
        }
        __syncwarp();
#pragma unroll
        for (int j = 0; j < 4; j++) {
            float2 tv = unpack_pair(T[j]);
            buf[j * 128 + 2 * lane] = fmaxf(tv.x, 0.f);
            buf[j * 128 + 2 * lane + 1] = fmaxf(tv.y, 0.f);
        }
        __syncwarp();
        u64 Z[4];
        u64 zb = pack_pair(sUB2[2 * lane], sUB2[2 * lane + 1]);
#pragma unroll
        for (int j = 0; j < 4; j++) Z[j] = zb;
#pragma unroll 4
        for (int i = 0; i < H; i += 4) {
            u64 w0 = *(const u64*)&sU2[(i + 0) * H + 2 * lane];
            u64 w1 = *(const u64*)&sU2[(i + 1) * H + 2 * lane];
            u64 w2 = *(const u64*)&sU2[(i + 2) * H + 2 * lane];
            u64 w3 = *(const u64*)&sU2[(i + 3) * H + 2 * lane];
#pragma unroll
            for (int j = 0; j < 4; j++) {
                float4 v = *(const float4*)&buf[j * 128 + i];
                fma2(Z[j], pack2(v.x), w0);
                fma2(Z[j], pack2(v.y), w1);
                fma2(Z[j], pack2(v.z), w2);
                fma2(Z[j], pack2(v.w), w3);
            }
        }
#pragma unroll
        for (int j = 0; j < 4; j++) {
            float2 zv = unpack_pair(Z[j]);
            *(float2*)&g_h[(base + j) * H + 2 * lane] =
                make_float2(fmaxf(zv.x, 0.f), fmaxf(zv.y, 0.f));
        }
        __syncwarp();
    }
}

// ---------------------------------------------------------------------------
__global__ void k_final(const int* __restrict__ n2g, float* __restrict__ out) {
    int wid = threadIdx.x >> 5, lane = threadIdx.x & 31;
    int nwarps = (blockDim.x >> 5) * gridDim.x;
    int gw = blockIdx.x * (blockDim.x >> 5) + wid;
    for (int n = gw; n < NN; n += nwarps) {
        int g = n2g[n];
        float2 hv = *(const float2*)&g_h[n * H + 2 * lane];
        red_add_v2(&out[g * H + 2 * lane], hv.x, hv.y);
        *(float2*)&out[NG * H + n * H + 2 * lane] = hv;
    }
}

// ---------------------------------------------------------------------------
extern "C" void kernel_launch(void* const* d_in, const int* in_sizes, int n_in,
                              void* d_out, int out_size) {
    const float* x        = (const float*)d_in[0];
    const int*   el       = (const int*)d_in[1];
    const int*   nstruct  = (const int*)d_in[2];
    const float* ef       = (const float*)d_in[3];
    const float* ew       = (const float*)d_in[4];
    const int*   n2g      = (const int*)d_in[5];
    const float* lin_w    = (const float*)d_in[7];
    const float* lin_b    = (const float*)d_in[8];
    const float* msg_w1   = (const float*)d_in[9];
    const float* msg_b1   = (const float*)d_in[10];
    const float* msg_w2   = (const float*)d_in[11];
    const float* msg_b2   = (const float*)d_in[12];
    const float* upd_w1   = (const float*)d_in[13];
    const float* upd_b1   = (const float*)d_in[14];
    const float* upd_w2   = (const float*)d_in[15];
    const float* upd_b2   = (const float*)d_in[16];
    float* out = (float*)d_out;

    static const size_t UPD_SMEM = (16576 + 8 * 512) * sizeof(float);
    cudaFuncSetAttribute(k_upd, cudaFuncAttributeMaxDynamicSharedMemorySize,
                         (int)UPD_SMEM);

    const int TPB = 256;
    const int NODE_BLOCKS = 1184;
    const int EDGE_BLOCKS = 1184;

    bool fork = g_sr.ok;
    cudaStream_t sc = fork ? g_sr.s2 : (cudaStream_t)0;

    if (fork) {
        cudaEventRecord(g_sr.ev_fork, 0);
        cudaStreamWaitEvent(sc, g_sr.ev_fork, 0);
    }

    // CSR build chain — forked stream (overlaps with h0 + layer-0 pq)
    k_zero<<<(NN + TPB - 1) / TPB, TPB, 0, sc>>>(out);
    k_deg<<<(NE + TPB - 1) / TPB, TPB, 0, sc>>>(el);
    k_scan_a<<<NSCANB, 256, 0, sc>>>();
    k_scan_b<<<1, 32, 0, sc>>>();
    k_scan_c<<<NSCANB, 256, 0, sc>>>();
    k_scatter<<<(NE + TPB - 1) / TPB, TPB, 0, sc>>>(el, ef, ew);
    if (fork) cudaEventRecord(g_sr.ev_join, sc);

    // Node-side work — main stream (independent of CSR chain)
    k_h0<<<NODE_BLOCKS, TPB>>>(x, lin_w, lin_b);
    k_pq<<<NODE_BLOCKS, TPB>>>(msg_w1, msg_b1, nstruct);

    if (fork) cudaStreamWaitEvent(0, g_sr.ev_join, 0);

    for (int l = 0; l < NL; l++) {
        const float* w1 = msg_w1 + (size_t)l * MSGIN * H;
        if (l > 0)
            k_pq<<<NODE_BLOCKS, TPB>>>(w1, msg_b1 + l * H, nstruct);
        k_edge_csr<<<EDGE_BLOCKS, TPB>>>(w1 + (2 * H + 2 * SCD) * H);
        k_upd<<<NODE_BLOCKS, TPB, UPD_SMEM>>>(
            msg_w2 + (size_t)l * H * H, msg_b2 + l * H,
            upd_w1 + (size_t)l * 2 * H * H, upd_b1 + l * H,
            upd_w2 + (size_t)l * H * H, upd_b2 + l * H);
    }

    k_final<<<NODE_BLOCKS, TPB>>>(n2g, out);
}